// round 5
// baseline (speedup 1.0000x reference)
#include <cuda_runtime.h>
#include <cstdint>

// Spatial correlation sampler: out[b, dh*9+dw, h, w] =
//   (1/C) * sum_c in1[b,c,h,w] * in2[b,c,h+dh-4,w+dw-4]   (zero-padded)
// B=8, C=256, H=128, W=256, patch=9.
//
// R5: scalar 8 px/thread (72 FFMA / 6 LDS.128 per channel), 288-thread CTAs
// (warp = dh), 2 CTAs/SM, ring-4 cp.async pipeline (CCH=2), hoisted loader.

#define BB   8
#define CC_  256
#define HH   128
#define WW   256
#define RAD  4
#define PATCH 9

#define TH   8
#define TW   32
#define CCH  2                        // channels per stage
#define NSTAGE 4                      // ring depth
#define ROWS2 (TH + 2*RAD)            // 16 in2 rows
#define P2   44                       // in2 row pitch (floats), 40 used  (44%32=12)
#define P1   36                       // in1 row pitch (floats), 32 used  (36%32=4)
#define IN2F (ROWS2 * P2)             // 704
#define CHF  (IN2F + TH * P1)         // 992 floats per channel
#define STAGEF (CCH * CHF)            // 1984 floats
#define STAGE_B (STAGEF * 4)          // 7936 bytes
#define IN2CK (ROWS2 * 10)            // 160 chunks per channel (in2, 40 floats/row)
#define CHCK  (IN2CK + TH * 8)        // 224 chunks per channel
#define TOTCK (CCH * CHCK)            // 448 chunks per stage
#define NT    288
#define NSTEPS (CC_ / CCH)            // 128 stages

__device__ __forceinline__ unsigned smem_u32(const void* p) {
    return (unsigned)__cvta_generic_to_shared(p);
}
__device__ __forceinline__ void cp16(unsigned dst, const void* src, int src_bytes) {
    asm volatile("cp.async.cg.shared.global [%0], [%1], 16, %2;\n"
                 :: "r"(dst), "l"(src), "r"(src_bytes));
}

__global__ void __launch_bounds__(NT, 2)
corr_kernel(const float* __restrict__ in1,
            const float* __restrict__ in2,
            float* __restrict__ out)
{
    __shared__ __align__(16) float sm[NSTAGE * STAGEF];   // 31744 B static

    const int tid  = threadIdx.x;
    const int lane = tid & 31;
    const int wg   = lane & 3;        // 4 w-groups x 8 px = 32 w
    const int hh   = lane >> 2;       // 0..7 rows
    const int dh   = tid >> 5;        // warp id = displacement row 0..8

    const int w0 = blockIdx.x * TW;
    const int h0 = blockIdx.y * TH;
    const int b  = blockIdx.z;

    const float* __restrict__ in1b = in1 + (size_t)b * CC_ * HH * WW;
    const float* __restrict__ in2b = in2 + (size_t)b * CC_ * HH * WW;

    // ---- hoisted loader slots (decoded once; per stage just advance) ----
    const unsigned smbase = smem_u32(sm);
    const unsigned smend  = smbase + NSTAGE * STAGE_B;

    const float* src0; unsigned dst0; int sz0;
    const float* src1 = in2b; unsigned dst1 = smbase; int sz1 = 0;
    const bool has1 = (tid < TOTCK - NT);   // tid < 160 owns a 2nd chunk

    auto decode = [&](int i, const float*& src, unsigned& dst, int& sz) {
        int ch = i / CHCK;                 // channel within stage 0..1
        int r  = i - ch * CHCK;
        sz = 16;
        if (r < IN2CK) {
            int row = r / 10;
            int ck  = r - row * 10;
            int gh = h0 - RAD + row;
            int gw = w0 - RAD + ck * 4;
            dst = smbase + (unsigned)(ch * CHF + row * P2 + ck * 4) * 4u;
            if (gh < 0 || gh >= HH || gw < 0 || gw >= WW) {
                sz = 0; src = in2b;        // full-chunk zero fill each stage
            } else {
                src = in2b + ((size_t)ch * HH + gh) * WW + gw;
            }
        } else {
            int r2 = r - IN2CK;
            int row = r2 >> 3;
            int ck  = r2 & 7;
            dst = smbase + (unsigned)(ch * CHF + IN2F + row * P1 + ck * 4) * 4u;
            src = in1b + ((size_t)ch * HH + (h0 + row)) * WW + (w0 + ck * 4);
        }
    };

    decode(tid, src0, dst0, sz0);
    if (has1) decode(tid + NT, src1, dst1, sz1);

    auto load_stage = [&]() {
        cp16(dst0, src0, sz0);
        src0 += CCH * HH * WW;
        dst0 += STAGE_B; if (dst0 >= smend) dst0 -= NSTAGE * STAGE_B;
        if (has1) {
            cp16(dst1, src1, sz1);
            src1 += CCH * HH * WW;
            dst1 += STAGE_B; if (dst1 >= smend) dst1 -= NSTAGE * STAGE_B;
        }
        asm volatile("cp.async.commit_group;\n");
    };

    // ---- accumulators: 9 dw x 8 px ----
    float acc[PATCH][8];
#pragma unroll
    for (int dw = 0; dw < PATCH; dw++)
#pragma unroll
        for (int j = 0; j < 8; j++) acc[dw][j] = 0.0f;

    const int off_win = (hh + dh) * P2 + wg * 8;     // in2 window [0..15]
    const int off_a   = IN2F + hh * P1 + wg * 8;     // in1 pixels [0..7]

    load_stage();   // stage 0
    load_stage();   // stage 1
    load_stage();   // stage 2

    const float* buf = sm;
    for (int s = 0; s < NSTEPS; s++) {
        asm volatile("cp.async.wait_group 2;\n");     // stage s resident
        __syncthreads();                               // all done with stage s-1
        if (s + 3 < NSTEPS) load_stage();              // -> slot (s-1)%4 (freed)
        else asm volatile("cp.async.commit_group;\n"); // keep group accounting

#pragma unroll
        for (int cc = 0; cc < CCH; cc++) {
            const float* chp = buf + cc * CHF;
            float4 q0 = *(const float4*)(chp + off_win);
            float4 q1 = *(const float4*)(chp + off_win + 4);
            float4 q2 = *(const float4*)(chp + off_win + 8);
            float4 q3 = *(const float4*)(chp + off_win + 12);
            float4 u0 = *(const float4*)(chp + off_a);
            float4 u1 = *(const float4*)(chp + off_a + 4);

            float win[16] = { q0.x,q0.y,q0.z,q0.w, q1.x,q1.y,q1.z,q1.w,
                              q2.x,q2.y,q2.z,q2.w, q3.x,q3.y,q3.z,q3.w };
            float a[8]    = { u0.x,u0.y,u0.z,u0.w, u1.x,u1.y,u1.z,u1.w };
#pragma unroll
            for (int dw = 0; dw < PATCH; dw++)
#pragma unroll
                for (int j = 0; j < 8; j++)
                    acc[dw][j] = fmaf(a[j], win[j + dw], acc[dw][j]);
        }

        buf += STAGEF;
        if (buf >= sm + NSTAGE * STAGEF) buf = sm;
    }

    // ---- epilogue: 9 dw x 8 floats per thread ----
    const float scale = 1.0f / (float)CC_;
    float* outp = out + (((size_t)b * (PATCH * PATCH) + dh * PATCH) * HH + (h0 + hh)) * WW
                      + (w0 + wg * 8);
#pragma unroll
    for (int dw = 0; dw < PATCH; dw++) {
        float4 A = make_float4(acc[dw][0]*scale, acc[dw][1]*scale,
                               acc[dw][2]*scale, acc[dw][3]*scale);
        float4 B = make_float4(acc[dw][4]*scale, acc[dw][5]*scale,
                               acc[dw][6]*scale, acc[dw][7]*scale);
        float* p = outp + (size_t)dw * HH * WW;
        *(float4*)p       = A;
        *(float4*)(p + 4) = B;
    }
}

extern "C" void kernel_launch(void* const* d_in, const int* in_sizes, int n_in,
                              void* d_out, int out_size)
{
    const float* in1 = (const float*)d_in[0];
    const float* in2 = (const float*)d_in[1];
    float* out = (float*)d_out;

    dim3 grid(WW / TW, HH / TH, BB);   // 8 x 16 x 8 = 1024 blocks
    dim3 block(NT);
    corr_kernel<<<grid, block>>>(in1, in2, out);
}

// round 6
// speedup vs baseline: 1.1502x; 1.1502x over previous
#include <cuda_runtime.h>
#include <cstdint>

// Spatial correlation sampler: out[b, dh*9+dw, h, w] =
//   (1/C) * sum_c in1[b,c,h,w] * in2[b,c,h+dh-4,w+dw-4]   (zero-padded)
// B=8, C=256, H=128, W=256, patch=9.
//
// R6 = R4 skeleton (576 thr, 4 px/thread, CCH=4, ring-3, hoisted loader)
// with fma.rn.f32x2 compute: even pairs free from LDS.128 register pairs,
// 5 odd pairs built with MOVs, 18 FFMA2 per channel instead of 36 FFMA.

#define BB   8
#define CC_  256
#define HH   128
#define WW   256
#define RAD  4
#define PATCH 9

#define TH   8
#define TW   32
#define CCH  4                        // channels per stage
#define NSTAGE 3                      // ring depth
#define ROWS2 (TH + 2*RAD)            // 16 in2 rows
#define PITCH2 44                     // in2 row pitch (floats), 40 used
#define IN2F  (ROWS2 * PITCH2)        // 704
#define CHF   (IN2F + TH * TW)        // 960 floats per channel
#define STAGEF (CCH * CHF)            // 3840 floats
#define STAGE_B (STAGEF * 4)          // 15360 bytes
#define IN2CK (ROWS2 * 11)            // 176 chunks per channel (in2)
#define CHCK  (IN2CK + TH * 8)        // 240 chunks per channel
#define TOTCK (CCH * CHCK)            // 960 chunks per stage
#define NT    576
#define NSTEPS (CC_ / CCH)            // 64 stages

__device__ __forceinline__ unsigned smem_u32(const void* p) {
    return (unsigned)__cvta_generic_to_shared(p);
}
__device__ __forceinline__ void cp16(unsigned dst, const void* src, int src_bytes) {
    asm volatile("cp.async.cg.shared.global [%0], [%1], 16, %2;\n"
                 :: "r"(dst), "l"(src), "r"(src_bytes));
}
__device__ __forceinline__ void fma2(unsigned long long& d,
                                     unsigned long long a, unsigned long long b) {
    asm("fma.rn.f32x2 %0, %1, %2, %3;" : "=l"(d) : "l"(a), "l"(b), "l"(d));
}
__device__ __forceinline__ unsigned long long mk2(unsigned lo, unsigned hi) {
    unsigned long long v;
    asm("mov.b64 %0, {%1, %2};" : "=l"(v) : "r"(lo), "r"(hi));
    return v;
}
__device__ __forceinline__ void un2(unsigned& lo, unsigned& hi, unsigned long long v) {
    asm("mov.b64 {%0, %1}, %2;" : "=r"(lo), "=r"(hi) : "l"(v));
}
__device__ __forceinline__ void unf(float& lo, float& hi, unsigned long long v) {
    asm("mov.b64 {%0, %1}, %2;" : "=f"(lo), "=f"(hi) : "l"(v));
}

__global__ void __launch_bounds__(NT, 1)
corr_kernel(const float* __restrict__ in1,
            const float* __restrict__ in2,
            float* __restrict__ out)
{
    __shared__ __align__(16) float sm[NSTAGE * STAGEF];   // 46080 B static

    const int tid = threadIdx.x;
    const int wg  = tid & 7;          // 8 w-groups x 4 px = 32 w
    const int hh  = (tid >> 3) & 7;   // row within tile
    const int dh  = tid >> 6;         // displacement row 0..8

    const int w0 = blockIdx.x * TW;
    const int h0 = blockIdx.y * TH;
    const int b  = blockIdx.z;

    const float* __restrict__ in1b = in1 + (size_t)b * CC_ * HH * WW;
    const float* __restrict__ in2b = in2 + (size_t)b * CC_ * HH * WW;

    // ---- hoisted loader slots ----
    const unsigned smbase = smem_u32(sm);
    const unsigned smend  = smbase + NSTAGE * STAGE_B;

    const float* src0; unsigned dst0; int sz0;
    const float* src1 = in2b; unsigned dst1 = smbase; int sz1 = 0;
    const bool has1 = (tid < TOTCK - NT);   // tid < 384 owns a 2nd chunk

    auto decode = [&](int i, const float*& src, unsigned& dst, int& sz) {
        int ch = i / CHCK;
        int r  = i - ch * CHCK;
        sz = 16;
        if (r < IN2CK) {
            int row = r / 11;
            int ck  = r - row * 11;
            int gh = h0 - RAD + row;
            int gw = w0 - RAD + ck * 4;
            dst = smbase + (unsigned)(ch * CHF + row * PITCH2 + ck * 4) * 4u;
            if (gh < 0 || gh >= HH || gw < 0 || gw >= WW) {
                sz = 0; src = in2b;        // full-chunk zero fill each stage
            } else {
                src = in2b + ((size_t)ch * HH + gh) * WW + gw;
            }
        } else {
            int r2 = r - IN2CK;
            int row = r2 >> 3;
            int ck  = r2 & 7;
            dst = smbase + (unsigned)(ch * CHF + IN2F + row * TW + ck * 4) * 4u;
            src = in1b + ((size_t)ch * HH + (h0 + row)) * WW + (w0 + ck * 4);
        }
    };

    decode(tid, src0, dst0, sz0);
    if (has1) decode(tid + NT, src1, dst1, sz1);

    auto load_stage = [&]() {
        cp16(dst0, src0, sz0);
        src0 += CCH * HH * WW;
        dst0 += STAGE_B; if (dst0 >= smend) dst0 -= NSTAGE * STAGE_B;
        if (has1) {
            cp16(dst1, src1, sz1);
            src1 += CCH * HH * WW;
            dst1 += STAGE_B; if (dst1 >= smend) dst1 -= NSTAGE * STAGE_B;
        }
        asm volatile("cp.async.commit_group;\n");
    };

    // ---- accumulators: 9 dw x 2 px-pairs ----
    unsigned long long acc[PATCH][2];
#pragma unroll
    for (int dw = 0; dw < PATCH; dw++) {
        acc[dw][0] = 0ull; acc[dw][1] = 0ull;
    }

    const int off_win = (hh + dh) * PITCH2 + wg * 4;     // floats, %4==0
    const int off_a   = IN2F + hh * TW + wg * 4;         // floats, %4==0

    load_stage();   // stage 0
    load_stage();   // stage 1

    const float* buf = sm;
    for (int s = 0; s < NSTEPS; s++) {
        asm volatile("cp.async.wait_group 1;\n");
        __syncthreads();
        if (s + 2 < NSTEPS) load_stage();
        else asm volatile("cp.async.commit_group;\n");

#pragma unroll
        for (int cc = 0; cc < CCH; cc++) {
            const float* chp = buf + cc * CHF;
            // window floats f0..f11 as aligned u64 pairs (free from LDS.128)
            ulonglong2 w01 = *(const ulonglong2*)(chp + off_win);
            ulonglong2 w23 = *(const ulonglong2*)(chp + off_win + 4);
            ulonglong2 w45 = *(const ulonglong2*)(chp + off_win + 8);
            ulonglong2 av  = *(const ulonglong2*)(chp + off_a);

            unsigned long long we[6] = { w01.x, w01.y, w23.x, w23.y, w45.x, w45.y };
            // odd pairs wo[t] = (f(2t+1), f(2t+2)) = (hi(we[t]), lo(we[t+1]))
            unsigned long long wo[5];
#pragma unroll
            for (int t = 0; t < 5; t++) {
                unsigned l0, h0_, l1, h1_;
                un2(l0, h0_, we[t]);
                un2(l1, h1_, we[t + 1]);
                wo[t] = mk2(h0_, l1);
            }

            const unsigned long long aX = av.x;   // (a0,a1)
            const unsigned long long aY = av.y;   // (a2,a3)
#pragma unroll
            for (int t = 0; t < 5; t++) {         // even dw = 2t
                fma2(acc[2*t][0], aX, we[t]);
                fma2(acc[2*t][1], aY, we[t + 1]);
            }
#pragma unroll
            for (int t = 0; t < 4; t++) {         // odd dw = 2t+1
                fma2(acc[2*t+1][0], aX, wo[t]);
                fma2(acc[2*t+1][1], aY, wo[t + 1]);
            }
        }

        buf += STAGEF;
        if (buf >= sm + NSTAGE * STAGEF) buf = sm;
    }

    // ---- epilogue ----
    const float scale = 1.0f / (float)CC_;
    float* outp = out + (((size_t)b * (PATCH * PATCH) + dh * PATCH) * HH + (h0 + hh)) * WW
                      + (w0 + wg * 4);
#pragma unroll
    for (int dw = 0; dw < PATCH; dw++) {
        float v0, v1, v2, v3;
        unf(v0, v1, acc[dw][0]);
        unf(v2, v3, acc[dw][1]);
        float4 v = make_float4(v0 * scale, v1 * scale, v2 * scale, v3 * scale);
        *(float4*)(outp + (size_t)dw * HH * WW) = v;
    }
}

extern "C" void kernel_launch(void* const* d_in, const int* in_sizes, int n_in,
                              void* d_out, int out_size)
{
    const float* in1 = (const float*)d_in[0];
    const float* in2 = (const float*)d_in[1];
    float* out = (float*)d_out;

    dim3 grid(WW / TW, HH / TH, BB);   // 8 x 16 x 8 = 1024 blocks
    dim3 block(NT);
    corr_kernel<<<grid, block>>>(in1, in2, out);
}

// round 7
// speedup vs baseline: 1.2253x; 1.0653x over previous
#include <cuda_runtime.h>
#include <cstdint>

// Spatial correlation sampler: out[b, dh*9+dw, h, w] =
//   (1/C) * sum_c in1[b,c,h,w] * in2[b,c,h+dh-4,w+dw-4]   (zero-padded)
// B=8, C=256, H=128, W=256, patch=9.
//
// R7 = R4 skeleton, compute body only changed:
//   even dw (5): fma.rn.f32x2 on natively-aligned pairs (zero MOVs)
//   odd  dw (4): scalar FFMA on individual floats (zero MOVs)
// 26 FMA-pipe ops per channel instead of 36.

#define BB   8
#define CC_  256
#define HH   128
#define WW   256
#define RAD  4
#define PATCH 9

#define TH   8
#define TW   32
#define CCH  4                        // channels per stage
#define NSTAGE 3                      // ring depth
#define ROWS2 (TH + 2*RAD)            // 16 in2 rows
#define PITCH2 44                     // in2 row pitch (floats), 40 used
#define IN2F  (ROWS2 * PITCH2)        // 704
#define CHF   (IN2F + TH * TW)        // 960 floats per channel
#define STAGEF (CCH * CHF)            // 3840 floats
#define STAGE_B (STAGEF * 4)          // 15360 bytes
#define IN2CK (ROWS2 * 11)            // 176 chunks per channel (in2)
#define CHCK  (IN2CK + TH * 8)        // 240 chunks per channel
#define TOTCK (CCH * CHCK)            // 960 chunks per stage
#define NT    576
#define NSTEPS (CC_ / CCH)            // 64 stages

__device__ __forceinline__ unsigned smem_u32(const void* p) {
    return (unsigned)__cvta_generic_to_shared(p);
}
__device__ __forceinline__ void cp16(unsigned dst, const void* src, int src_bytes) {
    asm volatile("cp.async.cg.shared.global [%0], [%1], 16, %2;\n"
                 :: "r"(dst), "l"(src), "r"(src_bytes));
}
__device__ __forceinline__ void fma2(unsigned long long& d,
                                     unsigned long long a, unsigned long long b) {
    asm("fma.rn.f32x2 %0, %1, %2, %3;" : "=l"(d) : "l"(a), "l"(b), "l"(d));
}
__device__ __forceinline__ void unf(float& lo, float& hi, unsigned long long v) {
    asm("mov.b64 {%0, %1}, %2;" : "=f"(lo), "=f"(hi) : "l"(v));
}

__global__ void __launch_bounds__(NT, 1)
corr_kernel(const float* __restrict__ in1,
            const float* __restrict__ in2,
            float* __restrict__ out)
{
    __shared__ __align__(16) float sm[NSTAGE * STAGEF];   // 46080 B static

    const int tid = threadIdx.x;
    const int wg  = tid & 7;          // 8 w-groups x 4 px = 32 w
    const int hh  = (tid >> 3) & 7;   // row within tile
    const int dh  = tid >> 6;         // displacement row 0..8

    const int w0 = blockIdx.x * TW;
    const int h0 = blockIdx.y * TH;
    const int b  = blockIdx.z;

    const float* __restrict__ in1b = in1 + (size_t)b * CC_ * HH * WW;
    const float* __restrict__ in2b = in2 + (size_t)b * CC_ * HH * WW;

    // ---- hoisted loader slots ----
    const unsigned smbase = smem_u32(sm);
    const unsigned smend  = smbase + NSTAGE * STAGE_B;

    const float* src0; unsigned dst0; int sz0;
    const float* src1 = in2b; unsigned dst1 = smbase; int sz1 = 0;
    const bool has1 = (tid < TOTCK - NT);   // tid < 384 owns a 2nd chunk

    auto decode = [&](int i, const float*& src, unsigned& dst, int& sz) {
        int ch = i / CHCK;
        int r  = i - ch * CHCK;
        sz = 16;
        if (r < IN2CK) {
            int row = r / 11;
            int ck  = r - row * 11;
            int gh = h0 - RAD + row;
            int gw = w0 - RAD + ck * 4;
            dst = smbase + (unsigned)(ch * CHF + row * PITCH2 + ck * 4) * 4u;
            if (gh < 0 || gh >= HH || gw < 0 || gw >= WW) {
                sz = 0; src = in2b;        // full-chunk zero fill each stage
            } else {
                src = in2b + ((size_t)ch * HH + gh) * WW + gw;
            }
        } else {
            int r2 = r - IN2CK;
            int row = r2 >> 3;
            int ck  = r2 & 7;
            dst = smbase + (unsigned)(ch * CHF + IN2F + row * TW + ck * 4) * 4u;
            src = in1b + ((size_t)ch * HH + (h0 + row)) * WW + (w0 + ck * 4);
        }
    };

    decode(tid, src0, dst0, sz0);
    if (has1) decode(tid + NT, src1, dst1, sz1);

    auto load_stage = [&]() {
        cp16(dst0, src0, sz0);
        src0 += CCH * HH * WW;
        dst0 += STAGE_B; if (dst0 >= smend) dst0 -= NSTAGE * STAGE_B;
        if (has1) {
            cp16(dst1, src1, sz1);
            src1 += CCH * HH * WW;
            dst1 += STAGE_B; if (dst1 >= smend) dst1 -= NSTAGE * STAGE_B;
        }
        asm volatile("cp.async.commit_group;\n");
    };

    // ---- accumulators ----
    // even dw (0,2,4,6,8): u64 pairs accE[t][0]=(px0,px1), accE[t][1]=(px2,px3)
    // odd  dw (1,3,5,7):   scalar accO[t][0..3]
    unsigned long long accE[5][2];
    float accO[4][4];
#pragma unroll
    for (int t = 0; t < 5; t++) { accE[t][0] = 0ull; accE[t][1] = 0ull; }
#pragma unroll
    for (int t = 0; t < 4; t++)
#pragma unroll
        for (int j = 0; j < 4; j++) accO[t][j] = 0.0f;

    const int off_win = (hh + dh) * PITCH2 + wg * 4;     // floats, %4==0
    const int off_a   = IN2F + hh * TW + wg * 4;         // floats, %4==0

    load_stage();   // stage 0
    load_stage();   // stage 1

    const float* buf = sm;
    for (int s = 0; s < NSTEPS; s++) {
        asm volatile("cp.async.wait_group 1;\n");
        __syncthreads();
        if (s + 2 < NSTEPS) load_stage();
        else asm volatile("cp.async.commit_group;\n");

#pragma unroll
        for (int cc = 0; cc < CCH; cc++) {
            const float* chp = buf + cc * CHF;
            // window f0..f11: loaded as 3 x LDS.128; u64 views of the same regs
            ulonglong2 w01 = *(const ulonglong2*)(chp + off_win);       // (f0,f1),(f2,f3)
            ulonglong2 w23 = *(const ulonglong2*)(chp + off_win + 4);   // (f4,f5),(f6,f7)
            ulonglong2 w45 = *(const ulonglong2*)(chp + off_win + 8);   // (f8,f9),(f10,f11)
            ulonglong2 av  = *(const ulonglong2*)(chp + off_a);         // (a0,a1),(a2,a3)

            unsigned long long we[6] = { w01.x, w01.y, w23.x, w23.y, w45.x, w45.y };
            const unsigned long long aX = av.x;
            const unsigned long long aY = av.y;

            // scalar views (same registers, no MOVs)
            float f[12], a[4];
            unf(f[0],  f[1],  we[0]); unf(f[2],  f[3],  we[1]);
            unf(f[4],  f[5],  we[2]); unf(f[6],  f[7],  we[3]);
            unf(f[8],  f[9],  we[4]); unf(f[10], f[11], we[5]);
            unf(a[0], a[1], aX); unf(a[2], a[3], aY);

            // even dw = 2t: acc(px0,px1) += (a0,a1)*(f[2t],f[2t+1]); (px2,px3) similar
#pragma unroll
            for (int t = 0; t < 5; t++) {
                fma2(accE[t][0], aX, we[t]);
                fma2(accE[t][1], aY, we[t + 1]);
            }
            // odd dw = 2t+1: scalar
#pragma unroll
            for (int t = 0; t < 4; t++) {
                const int d = 2 * t + 1;
#pragma unroll
                for (int j = 0; j < 4; j++)
                    accO[t][j] = fmaf(a[j], f[j + d], accO[t][j]);
            }
        }

        buf += STAGEF;
        if (buf >= sm + NSTAGE * STAGEF) buf = sm;
    }

    // ---- epilogue ----
    const float scale = 1.0f / (float)CC_;
    float* outp = out + (((size_t)b * (PATCH * PATCH) + dh * PATCH) * HH + (h0 + hh)) * WW
                      + (w0 + wg * 4);
#pragma unroll
    for (int t = 0; t < 5; t++) {              // even dw = 2t
        float v0, v1, v2, v3;
        unf(v0, v1, accE[t][0]);
        unf(v2, v3, accE[t][1]);
        float4 v = make_float4(v0 * scale, v1 * scale, v2 * scale, v3 * scale);
        *(float4*)(outp + (size_t)(2 * t) * HH * WW) = v;
    }
#pragma unroll
    for (int t = 0; t < 4; t++) {              // odd dw = 2t+1
        float4 v = make_float4(accO[t][0] * scale, accO[t][1] * scale,
                               accO[t][2] * scale, accO[t][3] * scale);
        *(float4*)(outp + (size_t)(2 * t + 1) * HH * WW) = v;
    }
}

extern "C" void kernel_launch(void* const* d_in, const int* in_sizes, int n_in,
                              void* d_out, int out_size)
{
    const float* in1 = (const float*)d_in[0];
    const float* in2 = (const float*)d_in[1];
    float* out = (float*)d_out;

    dim3 grid(WW / TW, HH / TH, BB);   // 8 x 16 x 8 = 1024 blocks
    dim3 block(NT);
    corr_kernel<<<grid, block>>>(in1, in2, out);
}